// round 4
// baseline (speedup 1.0000x reference)
#include <cuda_runtime.h>
#include <cuda_bf16.h>

// fast softplus: max(x,0) + log(1 + exp(-|x|)); abs error ~1e-7, tolerance is 1e-3
__device__ __forceinline__ float softplus_f(float x) {
    return fmaxf(x, 0.0f) + __logf(1.0f + __expf(-fabsf(x)));
}

// One CTA per batch row, NTHREADS threads, T <= CHUNK*NTHREADS.
// Phase 1a: batch-load CHUNK float4 per thread (coalesced, 8 LDG.128 in flight).
// Phase 1b: compute (ts, f) per element, stage to SMEM (8B/elem, coalesced STS).
// Phase 2 : per-thread sequential prefix over contiguous chunk reading (ts,f)
//           from SMEM (left neighbor included -> no shuffles, no boundary LDG),
//           then two-level block scan, then vectorized writes.
template <int CHUNK, int NTHREADS>
__global__ __launch_bounds__(NTHREADS, 1)
void soc_kernel(const float4* __restrict__ X,       // (B, T, 4)
                const float*  __restrict__ SC,      // (B, 4)
                const float*  __restrict__ W1i, const float* __restrict__ b1i,
                const float*  __restrict__ W2i, const float* __restrict__ b2i,
                const float*  __restrict__ W1e, const float* __restrict__ b1e,
                const float*  __restrict__ W2e, const float* __restrict__ b2e,
                float* __restrict__ out,            // (B, T)
                int T)
{
    constexpr int NELEM = CHUNK * NTHREADS;
    __shared__ float ts_s[NELEM];              // 32 KB
    __shared__ float f_s [NELEM];              // 32 KB
    __shared__ float warp_tot[NTHREADS / 32];

    const int b    = blockIdx.x;
    const int tid  = threadIdx.x;
    const long long rowbase = (long long)b * (long long)T;

    // Per-batch scalars
    const float Q    = SC[b * 4 + 0];
    const float eta0 = SC[b * 4 + 1];
    const float R    = SC[b * 4 + 2];
    const float S3   = SC[b * 4 + 3];

    const float w1e0 = W1e[0], w1e1 = W1e[1];
    const float be1  = b1e[0];
    const float w2e  = W2e[0];
    const float be2  = b2e[0];
    const float scale = eta0 / (3600.0f * Q);

    // ---- Phase 1a: batch all loads first (max MLP) ----
    float4 xv[CHUNK];
    #pragma unroll
    for (int j = 0; j < CHUNK; j++) {
        const int e = j * NTHREADS + tid;
        if (e < T) xv[j] = X[rowbase + e];     // warp: 512B contiguous
    }

    // SOC_init from t=0 features (broadcast load, hits L1)
    float4 x0 = X[rowbase];
    float h0 = softplus_f(x0.y * W1i[0] + x0.z * W1i[1] + x0.w * W1i[2] + R * W1i[3] + b1i[0]);
    const float SOC_init = S3 * (1.0f + (h0 * W2i[0] + b2i[0]));

    // ---- Phase 1b: compute (ts, f), stage to SMEM ----
    #pragma unroll
    for (int j = 0; j < CHUNK; j++) {
        const int e = j * NTHREADS + tid;
        if (e < T) {
            float h = softplus_f(fmaf(xv[j].y, w1e0, fmaf(xv[j].z, w1e1, be1)));
            float f = scale * (1.0f + fmaf(h, w2e, be2)) * xv[j].y;
            ts_s[e] = xv[j].x;                 // coalesced STS
            f_s [e] = f;
        }
    }
    __syncthreads();

    // ---- Phase 2: per-thread sequential prefix over contiguous chunk ----
    const int s = tid * CHUNK;
    float vals[CHUNK];
    float run = 0.0f;
    {
        float pts = 0.0f, pf = 0.0f;
        if (s > 0 && s <= T) { pts = ts_s[s - 1]; pf = f_s[s - 1]; }
        #pragma unroll
        for (int j = 0; j < CHUNK; j++) {
            const int t = s + j;
            if (t < T) {
                float ct = ts_s[t];
                if (t > 0) run += (ct - pts) * pf;   // dt * f[t-1]
                pts = ct;
                pf  = f_s[t];
            }
            vals[j] = run;
        }
    }

    // ---- Block-level exclusive scan of per-thread totals ----
    const unsigned FULL = 0xFFFFFFFFu;
    const int lane = tid & 31;
    const int warp = tid >> 5;

    float v = run;  // warp-inclusive scan
    #pragma unroll
    for (int d = 1; d < 32; d <<= 1) {
        float o = __shfl_up_sync(FULL, v, d);
        if (lane >= d) v += o;
    }
    if (lane == 31) warp_tot[warp] = v;
    __syncthreads();

    if (warp == 0) {
        float w = warp_tot[lane];
        #pragma unroll
        for (int d = 1; d < 32; d <<= 1) {
            float o = __shfl_up_sync(FULL, w, d);
            if (lane >= d) w += o;
        }
        warp_tot[lane] = w;
    }
    __syncthreads();

    const float warp_off = (warp > 0) ? warp_tot[warp - 1] : 0.0f;
    const float base     = SOC_init + warp_off + (v - run);  // exclusive prefix

    // ---- Write out ----
    if (s + CHUNK <= T) {
        float4* o4 = reinterpret_cast<float4*>(out + rowbase + s);
        #pragma unroll
        for (int k = 0; k < CHUNK / 4; k++) {
            float4 ov;
            ov.x = base + vals[k * 4 + 0];
            ov.y = base + vals[k * 4 + 1];
            ov.z = base + vals[k * 4 + 2];
            ov.w = base + vals[k * 4 + 3];
            o4[k] = ov;
        }
    } else {
        for (int j = 0; j < CHUNK; j++) {
            int t = s + j;
            if (t < T) out[rowbase + t] = base + vals[j];
        }
    }
}

extern "C" void kernel_launch(void* const* d_in, const int* in_sizes, int n_in,
                              void* d_out, int out_size)
{
    const float4* X  = (const float4*)d_in[0];   // (B, T, 4) fp32
    const float* SC  = (const float*)d_in[1];    // (B, 4)
    const float* W1i = (const float*)d_in[2];
    const float* b1i = (const float*)d_in[3];
    const float* W2i = (const float*)d_in[4];
    const float* b2i = (const float*)d_in[5];
    const float* W1e = (const float*)d_in[6];
    const float* b1e = (const float*)d_in[7];
    const float* W2e = (const float*)d_in[8];
    const float* b2e = (const float*)d_in[9];
    float* out = (float*)d_out;

    const int B = in_sizes[1] / 4;               // SC is (B,4)
    const int T = in_sizes[0] / (B * 4);         // X is (B,T,4)

    soc_kernel<8, 1024><<<B, 1024>>>(X, SC, W1i, b1i, W2i, b2i, W1e, b1e, W2e, b2e, out, T);
}

// round 5
// speedup vs baseline: 1.5901x; 1.5901x over previous
#include <cuda_runtime.h>
#include <cuda_bf16.h>
#include <cstdint>

// fast softplus: max(x,0) + log(1 + exp(-|x|)); abs error ~1e-7, tolerance is 1e-3
__device__ __forceinline__ float softplus_f(float x) {
    return fmaxf(x, 0.0f) + __logf(1.0f + __expf(-fabsf(x)));
}

__device__ __forceinline__ uint32_t smem_u32(const void* p) {
    return (uint32_t)__cvta_generic_to_shared(p);
}

#define MBAR_INIT(addr, cnt) \
    asm volatile("mbarrier.init.shared.b64 [%0], %1;" :: "r"(addr), "r"(cnt) : "memory")
#define MBAR_EXPECT_TX(addr, bytes) \
    asm volatile("mbarrier.arrive.expect_tx.shared.b64 _, [%0], %1;" :: "r"(addr), "r"(bytes) : "memory")
#define BULK_G2S(dst_smem, src_gmem, nbytes, bar) \
    asm volatile("cp.async.bulk.shared::cta.global.mbarrier::complete_tx::bytes [%0], [%1], %2, [%3];" \
                 :: "r"(dst_smem), "l"(src_gmem), "r"(nbytes), "r"(bar) : "memory")

__device__ __forceinline__ void mbar_wait_parity(uint32_t bar, uint32_t parity) {
    uint32_t done;
    asm volatile(
        "{\n\t.reg .pred p;\n\t"
        "mbarrier.try_wait.parity.acquire.cta.shared::cta.b64 p, [%1], %2;\n\t"
        "selp.b32 %0, 1, 0, p;\n\t}"
        : "=r"(done) : "r"(bar), "r"(parity) : "memory");
    while (!done) {
        asm volatile(
            "{\n\t.reg .pred p;\n\t"
            "mbarrier.try_wait.parity.acquire.cta.shared::cta.b64 p, [%1], %2, 0x989680;\n\t"
            "selp.b32 %0, 1, 0, p;\n\t}"
            : "=r"(done) : "r"(bar), "r"(parity) : "memory");
    }
}

// One CTA per batch row. Whole row (T*16B <= 128KB) staged into SMEM via
// cp.async.bulk in MAXCHUNK chunks, ALL issued up front (max MLP, no
// register pressure). Chunks processed in order behind mbarriers:
// 2 elems/thread prefix + two-level block scan, carry across chunks.
template <int NTHREADS, int CELEMS, int MAXCHUNK>
__global__ __launch_bounds__(NTHREADS, 1)
void soc_kernel(const float4* __restrict__ X,       // (B, T, 4)
                const float*  __restrict__ SC,      // (B, 4)
                const float*  __restrict__ W1i, const float* __restrict__ b1i,
                const float*  __restrict__ W2i, const float* __restrict__ b2i,
                const float*  __restrict__ W1e, const float* __restrict__ b1e,
                const float*  __restrict__ W2e, const float* __restrict__ b2e,
                float* __restrict__ out,            // (B, T)
                int T)
{
    extern __shared__ __align__(128) float4 xbuf[];    // MAXCHUNK * CELEMS float4
    __shared__ __align__(8) uint64_t mbar[MAXCHUNK];
    __shared__ float warp_tot[2][NTHREADS / 32];       // double-buffered
    __shared__ float bnd_ts, bnd_f;                    // chunk-boundary carry

    const int b    = blockIdx.x;
    const int tid  = threadIdx.x;
    const int lane = tid & 31;
    const int warp = tid >> 5;
    constexpr int NW = NTHREADS / 32;
    const unsigned FULL = 0xFFFFFFFFu;
    const long long rowbase = (long long)b * (long long)T;
    const int nchunks = (T + CELEMS - 1) / CELEMS;     // <= MAXCHUNK

    // ---- init barriers, then issue ALL bulk copies up front ----
    if (tid == 0) {
        #pragma unroll
        for (int c = 0; c < MAXCHUNK; c++)
            MBAR_INIT(smem_u32(&mbar[c]), 1);
    }
    __syncthreads();
    if (tid == 0) {
        for (int c = 0; c < nchunks; c++) {
            const int lim = min(CELEMS, T - c * CELEMS);
            const uint32_t nbytes = (uint32_t)lim * 16u;
            const uint32_t bar = smem_u32(&mbar[c]);
            MBAR_EXPECT_TX(bar, nbytes);
            BULK_G2S(smem_u32(&xbuf[c * CELEMS]),
                     (const void*)(X + rowbase + (long long)c * CELEMS),
                     nbytes, bar);
        }
    }

    // Per-batch scalars (overlaps with TMA flight)
    const float Q    = SC[b * 4 + 0];
    const float eta0 = SC[b * 4 + 1];
    const float R    = SC[b * 4 + 2];
    const float S3   = SC[b * 4 + 3];
    const float w1e0 = W1e[0], w1e1 = W1e[1];
    const float be1  = b1e[0];
    const float w2e  = W2e[0];
    const float be2  = b2e[0];
    const float w1i0 = W1i[0], w1i1 = W1i[1], w1i2 = W1i[2], w1i3 = W1i[3];
    const float bi1  = b1i[0], w2i = W2i[0], bi2 = b2i[0];
    const float scale = eta0 / (3600.0f * Q);

    float base = 0.0f;   // SOC_init + running cumsum carry (set at c==0)

    for (int c = 0; c < nchunks; c++) {
        mbar_wait_parity(smem_u32(&mbar[c]), 0);

        const float4* xb = &xbuf[c * CELEMS];
        const int lim = min(CELEMS, T - c * CELEMS);
        const int s = tid * 2;

        if (c == 0) {
            // SOC_init from t=0 features (broadcast LDS)
            float4 x0 = xb[0];
            float h0 = softplus_f(x0.y * w1i0 + x0.z * w1i1 + x0.w * w1i2 + R * w1i3 + bi1);
            base = S3 * (1.0f + (h0 * w2i + bi2));
        }

        float i0 = 0.0f, i1 = 0.0f;
        float lts = 0.0f, lf = 0.0f;      // this thread's last-element (ts,f) for bnd
        if (s < lim) {
            float4 v0 = xb[s];
            float ts0 = v0.x;
            float h0e = softplus_f(fmaf(v0.y, w1e0, fmaf(v0.z, w1e1, be1)));
            float f0  = scale * (1.0f + fmaf(h0e, w2e, be2)) * v0.y;
            lts = ts0; lf = f0;

            // left neighbor
            if (s == 0) {
                if (c > 0) i0 = (ts0 - bnd_ts) * bnd_f;   // read before sync1; written last chunk
            } else {
                float4 vn = xb[s - 1];
                float hn = softplus_f(fmaf(vn.y, w1e0, fmaf(vn.z, w1e1, be1)));
                float fn = scale * (1.0f + fmaf(hn, w2e, be2)) * vn.y;
                i0 = (ts0 - vn.x) * fn;
            }
            if (s + 1 < lim) {
                float4 v1 = xb[s + 1];
                i1 = (v1.x - ts0) * f0;
                float h1e = softplus_f(fmaf(v1.y, w1e0, fmaf(v1.z, w1e1, be1)));
                lts = v1.x;
                lf  = scale * (1.0f + fmaf(h1e, w2e, be2)) * v1.y;
            }
        }
        const float run = i0 + i1;

        // warp-inclusive scan of per-thread totals
        float v = run;
        #pragma unroll
        for (int d = 1; d < 32; d <<= 1) {
            float o = __shfl_up_sync(FULL, v, d);
            if (lane >= d) v += o;
        }
        const int cb = c & 1;
        if (lane == 31) warp_tot[cb][warp] = v;
        __syncthreads();                       // sync1: bnd reads done, warp_tot ready

        if (tid == ((lim - 1) >> 1)) { bnd_ts = lts; bnd_f = lf; }  // for next chunk
        if (warp == 0 && lane < NW) {
            float w = warp_tot[cb][lane];
            #pragma unroll
            for (int d = 1; d < NW; d <<= 1) {
                float o = __shfl_up_sync(FULL, w, d);
                if (lane >= d) w += o;
            }
            warp_tot[cb][lane] = w;
        }
        __syncthreads();                       // sync2

        const float warp_off = (warp > 0) ? warp_tot[cb][warp - 1] : 0.0f;
        const float excl = warp_off + (v - run);
        const float total = warp_tot[cb][NW - 1];

        // write out (float2 coalesced)
        if (s + 1 < lim) {
            float2 ov;
            ov.x = base + excl + i0;
            ov.y = base + excl + run;
            *reinterpret_cast<float2*>(out + rowbase + c * CELEMS + s) = ov;
        } else if (s < lim) {
            out[rowbase + c * CELEMS + s] = base + excl + i0;
        }

        base += total;
    }
}

extern "C" void kernel_launch(void* const* d_in, const int* in_sizes, int n_in,
                              void* d_out, int out_size)
{
    const float4* X  = (const float4*)d_in[0];   // (B, T, 4) fp32
    const float* SC  = (const float*)d_in[1];    // (B, 4)
    const float* W1i = (const float*)d_in[2];
    const float* b1i = (const float*)d_in[3];
    const float* W2i = (const float*)d_in[4];
    const float* b2i = (const float*)d_in[5];
    const float* W1e = (const float*)d_in[6];
    const float* b1e = (const float*)d_in[7];
    const float* W2e = (const float*)d_in[8];
    const float* b2e = (const float*)d_in[9];
    float* out = (float*)d_out;

    const int B = in_sizes[1] / 4;               // SC is (B,4)
    const int T = in_sizes[0] / (B * 4);         // X is (B,T,4)

    constexpr int NTH = 1024, CEL = 2048, MAXC = 4;
    const int smem_bytes = MAXC * CEL * 16;      // 128 KB
    static bool attr_set = false;
    if (!attr_set) {
        cudaFuncSetAttribute(soc_kernel<NTH, CEL, MAXC>,
                             cudaFuncAttributeMaxDynamicSharedMemorySize, smem_bytes);
        attr_set = true;
    }
    soc_kernel<NTH, CEL, MAXC><<<B, NTH, smem_bytes>>>(
        X, SC, W1i, b1i, W2i, b2i, W1e, b1e, W2e, b2e, out, T);
}